// round 2
// baseline (speedup 1.0000x reference)
#include <cuda_runtime.h>
#include <cstdint>

// ---------------------------------------------------------------------------
// BinarizeLinear: out[32768,512] = x[32768,512] @ sign(W)[512,512]  (fp32)
// Legacy tensor-core path (plain sm_100 target): mma.sync m16n8k8 tf32.
// CTA tile 128x128, BK=32, 3-stage cp.async pipeline, 8 warps (4x2),
// warp tile 32x64, fp32 padded smem (conflict-free fragment loads).
// ---------------------------------------------------------------------------

#define NT 32768
#define KD 512
#define ND 512

#define BM 128
#define BN 128
#define BK 32
#define STAGES 3
#define N_ITERS (KD / BK)        // 16

#define ROWF  (BK + 4)           // 36 floats per smem row (144B, 16B aligned)
#define TILEF (BM * ROWF)        // 4608 floats per tile
#define SLOTF (2 * TILEF)        // 9216 floats per stage (A + B)
#define SMEM_BYTES (STAGES * SLOTF * 4)   // 110592

// sign(W)^T, [N][K] row-major (K contiguous)
__device__ float g_BT[ND * KD];

// ---------------------------------------------------------------------------
__device__ __forceinline__ uint32_t su32(const void* p) {
    uint32_t a;
    asm("{ .reg .u64 t; cvta.to.shared.u64 t, %1; cvt.u32.u64 %0, t; }"
        : "=r"(a) : "l"(p));
    return a;
}

__device__ __forceinline__ void cp16(uint32_t s, const void* g) {
    asm volatile("cp.async.cg.shared.global [%0], [%1], 16;" :: "r"(s), "l"(g));
}

__device__ __forceinline__ uint32_t f2tf32(float f) {
    uint32_t u;
    asm("cvt.rna.tf32.f32 %0, %1;" : "=r"(u) : "f"(f));
    return u;
}

__device__ __forceinline__ void mma_tf32(float* d, const uint32_t* a, const uint32_t* b) {
    asm volatile(
        "mma.sync.aligned.m16n8k8.row.col.f32.tf32.tf32.f32 "
        "{%0,%1,%2,%3}, {%4,%5,%6,%7}, {%8,%9}, {%0,%1,%2,%3};"
        : "+f"(d[0]), "+f"(d[1]), "+f"(d[2]), "+f"(d[3])
        : "r"(a[0]), "r"(a[1]), "r"(a[2]), "r"(a[3]), "r"(b[0]), "r"(b[1]));
}

// ---------------------------------------------------------------------------
// Pre-kernel: g_BT[n*512 + k] = sign(W[k*512 + n])
// ---------------------------------------------------------------------------
__global__ void __launch_bounds__(256)
sign_transpose_kernel(const float* __restrict__ W) {
    int idx = blockIdx.x * 256 + threadIdx.x;   // 0 .. 262143
    int k = idx >> 9;
    int n = idx & 511;
    float w = W[idx];
    float s = (w > 0.0f) ? 1.0f : ((w < 0.0f) ? -1.0f : 0.0f);
    g_BT[n * KD + k] = s;
}

// ---------------------------------------------------------------------------
// Producer: fill one stage (A 128x32 from x, B 128x32 from g_BT), 1 commit.
// 2048 x 16B chunks total; 256 threads -> 8 chunks/thread.
// ---------------------------------------------------------------------------
__device__ __forceinline__ void produce(float* smem, int slot, int k0,
                                        int m_base, int n_base,
                                        const float* __restrict__ x, int tid) {
    uint32_t abase = su32(smem + slot * SLOTF);
    uint32_t bbase = abase + TILEF * 4u;
    #pragma unroll
    for (int i = 0; i < 4; ++i) {
        int c   = tid + i * 256;       // 0..1023
        int row = c >> 3;              // 0..127
        int kc  = c & 7;               // 0..7 (16B chunks)
        uint32_t off = (uint32_t)(row * ROWF + kc * 4) * 4u;
        cp16(abase + off, x    + (size_t)(m_base + row) * KD + k0 + kc * 4);
        cp16(bbase + off, g_BT + (size_t)(n_base + row) * KD + k0 + kc * 4);
    }
    asm volatile("cp.async.commit_group;" ::: "memory");
}

// ---------------------------------------------------------------------------
__global__ void __launch_bounds__(256, 1)
gemm_kernel(const float* __restrict__ x, float* __restrict__ out) {
    extern __shared__ float smem[];
    const int tid  = threadIdx.x;
    const int wid  = tid >> 5;
    const int lane = tid & 31;
    const int wr   = wid & 3;          // warp row: m offset wr*32
    const int wc   = wid >> 2;         // warp col: n offset wc*64
    const int g    = lane >> 2;        // groupID (0..7)
    const int t    = lane & 3;         // threadID in group (0..3)

    const int ntile  = blockIdx.x & 3;          // adjacent CTAs share A panel
    const int mtile  = blockIdx.x >> 2;
    const int m_base = mtile * BM;
    const int n_base = ntile * BN;

    float d[2][8][4];
    #pragma unroll
    for (int mt = 0; mt < 2; ++mt)
        #pragma unroll
        for (int nt = 0; nt < 8; ++nt)
            #pragma unroll
            for (int q = 0; q < 4; ++q) d[mt][nt][q] = 0.0f;

    // Prologue: fill stages 0 and 1
    produce(smem, 0, 0,  m_base, n_base, x, tid);
    produce(smem, 1, BK, m_base, n_base, x, tid);

    for (int it = 0; it < N_ITERS; ++it) {
        if (it < N_ITERS - 1) asm volatile("cp.async.wait_group 1;" ::: "memory");
        else                  asm volatile("cp.async.wait_group 0;" ::: "memory");
        __syncthreads();

        // Prefetch stage it+2 into the slot consumed at iteration it-1
        if (it + 2 < N_ITERS)
            produce(smem, (it + 2) % STAGES, (it + 2) * BK, m_base, n_base, x, tid);

        // Compute stage it
        const float* As = smem + (it % STAGES) * SLOTF;
        const float* Bs = As + TILEF;

        #pragma unroll
        for (int kk = 0; kk < 4; ++kk) {
            const int k0 = kk * 8;

            uint32_t a[2][4];
            #pragma unroll
            for (int mt = 0; mt < 2; ++mt) {
                const float* p = As + (wr * 32 + mt * 16 + g) * ROWF + k0 + t;
                a[mt][0] = f2tf32(p[0]);
                a[mt][1] = f2tf32(p[8 * ROWF]);
                a[mt][2] = f2tf32(p[4]);
                a[mt][3] = f2tf32(p[8 * ROWF + 4]);
            }

            uint32_t b[8][2];
            #pragma unroll
            for (int nt = 0; nt < 8; ++nt) {
                const float* p = Bs + (wc * 64 + nt * 8 + g) * ROWF + k0 + t;
                b[nt][0] = __float_as_uint(p[0]);   // ±1/0 exact in tf32
                b[nt][1] = __float_as_uint(p[4]);
            }

            #pragma unroll
            for (int mt = 0; mt < 2; ++mt)
                #pragma unroll
                for (int nt = 0; nt < 8; ++nt)
                    mma_tf32(d[mt][nt], a[mt], b[nt]);
        }
    }

    // Epilogue: direct register -> global stores (float2)
    #pragma unroll
    for (int mt = 0; mt < 2; ++mt) {
        const int r0 = m_base + wr * 32 + mt * 16 + g;
        #pragma unroll
        for (int nt = 0; nt < 8; ++nt) {
            const int c = n_base + wc * 64 + nt * 8 + t * 2;
            *reinterpret_cast<float2*>(out + (size_t)r0 * ND + c) =
                make_float2(d[mt][nt][0], d[mt][nt][1]);
            *reinterpret_cast<float2*>(out + (size_t)(r0 + 8) * ND + c) =
                make_float2(d[mt][nt][2], d[mt][nt][3]);
        }
    }
}

// ---------------------------------------------------------------------------
extern "C" void kernel_launch(void* const* d_in, const int* in_sizes, int n_in,
                              void* d_out, int out_size) {
    const float* x = (const float*)d_in[0];   // [32768, 512]
    const float* W = (const float*)d_in[1];   // [512, 512]
    float* out = (float*)d_out;               // [32768, 512]
    (void)in_sizes; (void)n_in; (void)out_size;

    cudaFuncSetAttribute(gemm_kernel,
                         cudaFuncAttributeMaxDynamicSharedMemorySize, SMEM_BYTES);

    sign_transpose_kernel<<<(KD * ND) / 256, 256>>>(W);
    gemm_kernel<<<(NT / BM) * (ND / BN), 256, SMEM_BYTES>>>(x, out);
}

// round 3
// speedup vs baseline: 1.4041x; 1.4041x over previous
#include <cuda_runtime.h>
#include <cstdint>

// ---------------------------------------------------------------------------
// BinarizeLinear: out[32768,512] = x[32768,512] @ sign(W)[512,512]  (fp32)
// mma.sync m16n8k8 tf32, CTA tile 128x128, BK=32, 3-stage cp.async pipeline,
// ldmatrix.x4 fragment loads, XOR-swizzled 128B smem rows, 2 CTAs/SM.
// ---------------------------------------------------------------------------

#define NT 32768
#define KD 512
#define ND 512

#define BM 128
#define BN 128
#define BK 32
#define STAGES 3
#define N_ITERS (KD / BK)            // 16

#define TILE_BYTES  16384            // 128 rows x 128B
#define SLOT_BYTES  32768            // A + B
#define SMEM_BYTES  (STAGES * SLOT_BYTES)   // 98304 -> 2 CTAs/SM

// sign(W)^T, [N][K] row-major (K contiguous)
__device__ float g_BT[ND * KD];

// ---------------------------------------------------------------------------
__device__ __forceinline__ uint32_t su32(const void* p) {
    uint32_t a;
    asm("{ .reg .u64 t; cvta.to.shared.u64 t, %1; cvt.u32.u64 %0, t; }"
        : "=r"(a) : "l"(p));
    return a;
}

__device__ __forceinline__ void cp16(uint32_t s, const void* g) {
    asm volatile("cp.async.cg.shared.global [%0], [%1], 16;" :: "r"(s), "l"(g));
}

__device__ __forceinline__ uint32_t f2tf32(uint32_t raw) {
    uint32_t u;
    asm("cvt.rna.tf32.f32 %0, %1;" : "=r"(u) : "r"(raw));
    return u;
}

__device__ __forceinline__ void ldsm4(uint32_t& r0, uint32_t& r1,
                                      uint32_t& r2, uint32_t& r3, uint32_t a) {
    asm volatile("ldmatrix.sync.aligned.m8n8.x4.shared.b16 {%0,%1,%2,%3}, [%4];"
                 : "=r"(r0), "=r"(r1), "=r"(r2), "=r"(r3) : "r"(a));
}

__device__ __forceinline__ void mma_tf32(float* d, const uint32_t* a, const uint32_t* b) {
    asm volatile(
        "mma.sync.aligned.m16n8k8.row.col.f32.tf32.tf32.f32 "
        "{%0,%1,%2,%3}, {%4,%5,%6,%7}, {%8,%9}, {%0,%1,%2,%3};"
        : "+f"(d[0]), "+f"(d[1]), "+f"(d[2]), "+f"(d[3])
        : "r"(a[0]), "r"(a[1]), "r"(a[2]), "r"(a[3]), "r"(b[0]), "r"(b[1]));
}

// ---------------------------------------------------------------------------
// Pre-kernel: g_BT[n*512 + k] = sign(W[k*512 + n])
// ---------------------------------------------------------------------------
__global__ void __launch_bounds__(256)
sign_transpose_kernel(const float* __restrict__ W) {
    int idx = blockIdx.x * 256 + threadIdx.x;
    int k = idx >> 9;
    int n = idx & 511;
    float w = W[idx];
    float s = (w > 0.0f) ? 1.0f : ((w < 0.0f) ? -1.0f : 0.0f);
    g_BT[n * KD + k] = s;
}

// ---------------------------------------------------------------------------
// Producer: fill one stage (A 128x32 + B 128x32 fp32, swizzled 128B rows).
// 2048 x 16B chunks; 256 threads -> 8 each.
// ---------------------------------------------------------------------------
__device__ __forceinline__ void produce(uint32_t sb, int slot, int k0,
                                        int m_base, int n_base,
                                        const float* __restrict__ x, int tid) {
    uint32_t abase = sb + (uint32_t)slot * SLOT_BYTES;
    uint32_t bbase = abase + TILE_BYTES;
    #pragma unroll
    for (int i = 0; i < 4; ++i) {
        int c   = tid + i * 256;       // 0..1023
        int row = c >> 3;              // 0..127
        int kc  = c & 7;               // 16B chunk within row
        uint32_t off = (uint32_t)row * 128u + (((uint32_t)kc * 16u) ^ (((uint32_t)row & 7u) << 4));
        cp16(abase + off, x    + (size_t)(m_base + row) * KD + k0 + kc * 4);
        cp16(bbase + off, g_BT + (size_t)(n_base + row) * KD + k0 + kc * 4);
    }
    asm volatile("cp.async.commit_group;" ::: "memory");
}

// ---------------------------------------------------------------------------
__global__ void __launch_bounds__(256, 2)
gemm_kernel(const float* __restrict__ x, float* __restrict__ out) {
    extern __shared__ float smem[];
    const uint32_t sb = su32(smem);
    const int tid  = threadIdx.x;
    const int wid  = tid >> 5;
    const int lane = tid & 31;
    const int wr   = wid & 3;          // warp row: m offset wr*32
    const int wc   = wid >> 2;         // warp col: n offset wc*64
    const int g    = lane >> 2;
    const int t    = lane & 3;

    const int ntile  = blockIdx.x & 3;          // adjacent CTAs share A panel
    const int mtile  = blockIdx.x >> 2;
    const int m_base = mtile * BM;
    const int n_base = ntile * BN;

    // ldmatrix lane->address precompute (swizzle mask depends only on lane&7)
    const uint32_t swz = ((uint32_t)(lane & 7)) << 4;
    // A: matrices ordered {rows-lo,k-lo},{rows-hi,k-lo},{rows-lo,k-hi},{rows-hi,k-hi}
    const uint32_t a_row   = (uint32_t)(wr * 32 + ((lane >> 3) & 1) * 8 + (lane & 7));
    const uint32_t a_khalf = (uint32_t)(((lane >> 4) & 1) * 16);
    const uint32_t a_off   = a_row * 128u;
    // B: matrices ordered {rows-lo,k-lo},{rows-lo,k-hi},{rows-hi,k-lo},{rows-hi,k-hi}
    const uint32_t b_row   = (uint32_t)(wc * 64 + ((lane >> 4) & 1) * 8 + (lane & 7));
    const uint32_t b_khalf = (uint32_t)(((lane >> 3) & 1) * 16);
    const uint32_t b_off   = b_row * 128u;

    float d[2][8][4];
    #pragma unroll
    for (int mt = 0; mt < 2; ++mt)
        #pragma unroll
        for (int nt = 0; nt < 8; ++nt)
            #pragma unroll
            for (int q = 0; q < 4; ++q) d[mt][nt][q] = 0.0f;

    produce(sb, 0, 0,  m_base, n_base, x, tid);
    produce(sb, 1, BK, m_base, n_base, x, tid);

    for (int it = 0; it < N_ITERS; ++it) {
        if (it < N_ITERS - 1) asm volatile("cp.async.wait_group 1;" ::: "memory");
        else                  asm volatile("cp.async.wait_group 0;" ::: "memory");
        __syncthreads();

        if (it + 2 < N_ITERS)
            produce(sb, (it + 2) % STAGES, (it + 2) * BK, m_base, n_base, x, tid);

        const uint32_t As  = sb + (uint32_t)(it % STAGES) * SLOT_BYTES;
        const uint32_t Bsm = As + TILE_BYTES;

        #pragma unroll
        for (int kk = 0; kk < 4; ++kk) {
            const uint32_t kb = (uint32_t)kk * 32u;   // bytes along K

            uint32_t a[2][4];
            {
                const uint32_t ka = (kb + a_khalf) ^ swz;
                ldsm4(a[0][0], a[0][1], a[0][2], a[0][3], As + a_off + ka);
                ldsm4(a[1][0], a[1][1], a[1][2], a[1][3], As + a_off + 2048u + ka);
            }
            uint32_t b[8][2];
            {
                const uint32_t kbb = (kb + b_khalf) ^ swz;
                #pragma unroll
                for (int j = 0; j < 4; ++j) {
                    ldsm4(b[2 * j][0], b[2 * j][1], b[2 * j + 1][0], b[2 * j + 1][1],
                          Bsm + b_off + (uint32_t)j * 2048u + kbb);
                }
            }
            // Round A to tf32 (B is exact +/-1/0)
            #pragma unroll
            for (int mt = 0; mt < 2; ++mt)
                #pragma unroll
                for (int q = 0; q < 4; ++q) a[mt][q] = f2tf32(a[mt][q]);

            #pragma unroll
            for (int mt = 0; mt < 2; ++mt)
                #pragma unroll
                for (int nt = 0; nt < 8; ++nt)
                    mma_tf32(d[mt][nt], a[mt], b[nt]);
        }
    }

    // Epilogue: register -> global float2 stores
    #pragma unroll
    for (int mt = 0; mt < 2; ++mt) {
        const int r0 = m_base + wr * 32 + mt * 16 + g;
        #pragma unroll
        for (int nt = 0; nt < 8; ++nt) {
            const int c = n_base + wc * 64 + nt * 8 + t * 2;
            *reinterpret_cast<float2*>(out + (size_t)r0 * ND + c) =
                make_float2(d[mt][nt][0], d[mt][nt][1]);
            *reinterpret_cast<float2*>(out + (size_t)(r0 + 8) * ND + c) =
                make_float2(d[mt][nt][2], d[mt][nt][3]);
        }
    }
}

// ---------------------------------------------------------------------------
extern "C" void kernel_launch(void* const* d_in, const int* in_sizes, int n_in,
                              void* d_out, int out_size) {
    const float* x = (const float*)d_in[0];   // [32768, 512]
    const float* W = (const float*)d_in[1];   // [512, 512]
    float* out = (float*)d_out;               // [32768, 512]
    (void)in_sizes; (void)n_in; (void)out_size;

    cudaFuncSetAttribute(gemm_kernel,
                         cudaFuncAttributeMaxDynamicSharedMemorySize, SMEM_BYTES);

    sign_transpose_kernel<<<(KD * ND) / 256, 256>>>(W);
    gemm_kernel<<<(NT / BM) * (ND / BN), 256, SMEM_BYTES>>>(x, out);
}

// round 7
// speedup vs baseline: 1.8510x; 1.3183x over previous
#include <cuda_runtime.h>
#include <cuda_fp16.h>
#include <cstdint>

// ---------------------------------------------------------------------------
// BinarizeLinear: out[32768,512] = x[32768,512] @ sign(W)[512,512]  (fp32)
// fp16 path: x pre-converted to fp16 (same 11-bit significand as tf32),
// B = sign(W) exact in fp16. mma.sync m16n8k16 f32.f16.f16.f32.
// CTA tile 128x128, BK=64 halves (128B rows), 3-stage cp.async, 2 CTAs/SM.
// ---------------------------------------------------------------------------

#define NT 32768
#define KD 512
#define ND 512

#define BM 128
#define BN 128
#define BK 64                         // halves per stage
#define STAGES 3
#define N_ITERS (KD / BK)             // 8

#define TILE_BYTES  16384             // 128 rows x 128B
#define SLOT_BYTES  32768
#define SMEM_BYTES  (STAGES * SLOT_BYTES)   // 98304 -> 2 CTAs/SM

// fp16 scratch: x and sign(W)^T ([N][K], K contiguous)
__device__ __half g_xh[NT * KD];      // 32 MB
__device__ __half g_BTh[ND * KD];     // 0.5 MB

// ---------------------------------------------------------------------------
__device__ __forceinline__ uint32_t su32(const void* p) {
    uint32_t a;
    asm("{ .reg .u64 t; cvta.to.shared.u64 t, %1; cvt.u32.u64 %0, t; }"
        : "=r"(a) : "l"(p));
    return a;
}

__device__ __forceinline__ void cp16(uint32_t s, const void* g) {
    asm volatile("cp.async.cg.shared.global [%0], [%1], 16;" :: "r"(s), "l"(g));
}

__device__ __forceinline__ uint32_t pack_h2(float lo, float hi) {
    uint32_t u;
    asm("cvt.rn.f16x2.f32 %0, %1, %2;" : "=r"(u) : "f"(hi), "f"(lo));
    return u;
}

__device__ __forceinline__ void ldsm4(uint32_t& r0, uint32_t& r1,
                                      uint32_t& r2, uint32_t& r3, uint32_t a) {
    asm volatile("ldmatrix.sync.aligned.m8n8.x4.shared.b16 {%0,%1,%2,%3}, [%4];"
                 : "=r"(r0), "=r"(r1), "=r"(r2), "=r"(r3) : "r"(a));
}

__device__ __forceinline__ void mma_f16(float* d, const uint32_t* a, const uint32_t* b) {
    asm volatile(
        "mma.sync.aligned.m16n8k16.row.col.f32.f16.f16.f32 "
        "{%0,%1,%2,%3}, {%4,%5,%6,%7}, {%8,%9}, {%0,%1,%2,%3};"
        : "+f"(d[0]), "+f"(d[1]), "+f"(d[2]), "+f"(d[3])
        : "r"(a[0]), "r"(a[1]), "r"(a[2]), "r"(a[3]), "r"(b[0]), "r"(b[1]));
}

// ---------------------------------------------------------------------------
// Pre-kernel 1: g_xh = (half)x   (8 floats/thread, vectorized)
// ---------------------------------------------------------------------------
__global__ void __launch_bounds__(256)
convert_x_kernel(const float4* __restrict__ x4) {
    int i = blockIdx.x * 256 + threadIdx.x;       // 0 .. 2097151
    float4 lo = x4[2 * i];
    float4 hi = x4[2 * i + 1];
    uint4 o;
    o.x = pack_h2(lo.x, lo.y);
    o.y = pack_h2(lo.z, lo.w);
    o.z = pack_h2(hi.x, hi.y);
    o.w = pack_h2(hi.z, hi.w);
    reinterpret_cast<uint4*>(g_xh)[i] = o;
}

// ---------------------------------------------------------------------------
// Pre-kernel 2: g_BTh[n*512 + k] = (half)sign(W[k*512 + n])
// ---------------------------------------------------------------------------
__global__ void __launch_bounds__(256)
sign_transpose_kernel(const float* __restrict__ W) {
    int idx = blockIdx.x * 256 + threadIdx.x;
    int k = idx >> 9;
    int n = idx & 511;
    float w = W[idx];
    // sign in fp16: +1 -> 0x3C00, -1 -> 0xBC00, 0 -> 0x0000
    unsigned short h = (w > 0.0f) ? (unsigned short)0x3C00
                     : ((w < 0.0f) ? (unsigned short)0xBC00 : (unsigned short)0);
    reinterpret_cast<unsigned short*>(g_BTh)[n * KD + k] = h;
}

// ---------------------------------------------------------------------------
// Producer: one stage = A 128x64h + B 128x64h (128B swizzled rows).
// 2048 x 16B chunks; 256 threads -> 8 each.
// ---------------------------------------------------------------------------
__device__ __forceinline__ void produce(uint32_t sb, int slot, int k0,
                                        int m_base, int n_base, int tid) {
    uint32_t abase = sb + (uint32_t)slot * SLOT_BYTES;
    uint32_t bbase = abase + TILE_BYTES;
    #pragma unroll
    for (int i = 0; i < 4; ++i) {
        int c   = tid + i * 256;       // 0..1023
        int row = c >> 3;              // 0..127
        int kc  = c & 7;               // 16B chunk within row
        uint32_t off = (uint32_t)row * 128u
                     + (((uint32_t)kc * 16u) ^ (((uint32_t)row & 7u) << 4));
        cp16(abase + off, g_xh  + (size_t)(m_base + row) * KD + k0 + kc * 8);
        cp16(bbase + off, g_BTh + (size_t)(n_base + row) * KD + k0 + kc * 8);
    }
    asm volatile("cp.async.commit_group;" ::: "memory");
}

// ---------------------------------------------------------------------------
__global__ void __launch_bounds__(256, 2)
gemm_kernel(float* __restrict__ out) {
    extern __shared__ float smem[];
    const uint32_t sb = su32(smem);
    const int tid  = threadIdx.x;
    const int wid  = tid >> 5;
    const int lane = tid & 31;
    const int wr   = wid & 3;          // warp row: m offset wr*32
    const int wc   = wid >> 2;         // warp col: n offset wc*64
    const int g    = lane >> 2;
    const int t    = lane & 3;

    const int ntile  = blockIdx.x & 3;          // adjacent CTAs share A panel
    const int mtile  = blockIdx.x >> 2;
    const int m_base = mtile * BM;
    const int n_base = ntile * BN;

    // ldmatrix addressing: row = lane&15 (within 16-row tile), k-half = lane>>4
    const uint32_t swz    = ((uint32_t)(lane & 7)) << 4;
    const uint32_t khalf  = ((uint32_t)(lane >> 4)) << 4;   // 0 or 16 bytes
    const uint32_t a_off  = (uint32_t)(wr * 32 + (lane & 15)) * 128u;
    const uint32_t b_off  = (uint32_t)(wc * 64 + (lane & 15)) * 128u;

    float d[2][8][4];
    #pragma unroll
    for (int mt = 0; mt < 2; ++mt)
        #pragma unroll
        for (int nt = 0; nt < 8; ++nt)
            #pragma unroll
            for (int q = 0; q < 4; ++q) d[mt][nt][q] = 0.0f;

    produce(sb, 0, 0,  m_base, n_base, tid);
    produce(sb, 1, BK, m_base, n_base, tid);

    for (int it = 0; it < N_ITERS; ++it) {
        if (it < N_ITERS - 1) asm volatile("cp.async.wait_group 1;" ::: "memory");
        else                  asm volatile("cp.async.wait_group 0;" ::: "memory");
        __syncthreads();

        if (it + 2 < N_ITERS)
            produce(sb, (it + 2) % STAGES, (it + 2) * BK, m_base, n_base, tid);

        const uint32_t As  = sb + (uint32_t)(it % STAGES) * SLOT_BYTES;
        const uint32_t Bsm = As + TILE_BYTES;

        #pragma unroll
        for (int kk = 0; kk < 4; ++kk) {
            const uint32_t kb = ((uint32_t)kk * 32u + khalf) ^ swz;   // bytes along K

            uint32_t a[2][4];
            ldsm4(a[0][0], a[0][1], a[0][2], a[0][3], As + a_off + kb);
            ldsm4(a[1][0], a[1][1], a[1][2], a[1][3], As + a_off + 2048u + kb);

            uint32_t b[8][2];
            #pragma unroll
            for (int j = 0; j < 4; ++j) {
                // 16 n-rows per ldsm4: m0=n[0:8)k-lo, m1=n[8:16)k-lo,
                //                      m2=n[0:8)k-hi, m3=n[8:16)k-hi
                ldsm4(b[2 * j][0], b[2 * j + 1][0], b[2 * j][1], b[2 * j + 1][1],
                      Bsm + b_off + (uint32_t)j * 2048u + kb);
            }

            #pragma unroll
            for (int mt = 0; mt < 2; ++mt)
                #pragma unroll
                for (int nt = 0; nt < 8; ++nt)
                    mma_f16(d[mt][nt], a[mt], b[nt]);
        }
    }

    // Epilogue: register -> global float2 stores
    #pragma unroll
    for (int mt = 0; mt < 2; ++mt) {
        const int r0 = m_base + wr * 32 + mt * 16 + g;
        #pragma unroll
        for (int nt = 0; nt < 8; ++nt) {
            const int c = n_base + wc * 64 + nt * 8 + t * 2;
            *reinterpret_cast<float2*>(out + (size_t)r0 * ND + c) =
                make_float2(d[mt][nt][0], d[mt][nt][1]);
            *reinterpret_cast<float2*>(out + (size_t)(r0 + 8) * ND + c) =
                make_float2(d[mt][nt][2], d[mt][nt][3]);
        }
    }
}

// ---------------------------------------------------------------------------
extern "C" void kernel_launch(void* const* d_in, const int* in_sizes, int n_in,
                              void* d_out, int out_size) {
    const float* x = (const float*)d_in[0];   // [32768, 512]
    const float* W = (const float*)d_in[1];   // [512, 512]
    float* out = (float*)d_out;               // [32768, 512]
    (void)in_sizes; (void)n_in; (void)out_size;

    cudaFuncSetAttribute(gemm_kernel,
                         cudaFuncAttributeMaxDynamicSharedMemorySize, SMEM_BYTES);

    convert_x_kernel<<<(NT * KD / 8) / 256, 256>>>((const float4*)x);
    sign_transpose_kernel<<<(KD * ND) / 256, 256>>>(W);
    gemm_kernel<<<(NT / BM) * (ND / BN), 256, SMEM_BYTES>>>(out);
}